// round 16
// baseline (speedup 1.0000x reference)
#include <cuda_runtime.h>
#include <cuda_fp16.h>
#include <math.h>
#include <stdint.h>

#define N_NODES 65536
#define N_EDGES 524288
#define C 128
#define L 3
#define BN_EPS 1e-5f

// ---------------- scratch (device globals; no dynamic allocation) ----------------
__device__ float  g_h[N_NODES * C];        // layer output fp32 (GEMM A input)
__device__ __half g_act16[N_NODES * C];    // fp16 copy of activations (gather input)
__device__ float  g_neigh[N_NODES * C];    // aggregated neighbor features (already /deg)
__device__ float  g_wbar[N_NODES];         // (sum of edge weights)/deg per node
__device__ float2 g_edge[N_EDGES];         // CSR-by-dst packed records: (src bits, log1p(w))
__device__ int    g_degcnt[N_NODES];
__device__ int    g_off[N_NODES + 1];
__device__ int    g_cursor[N_NODES];
__device__ float  g_deginv[N_NODES];
__device__ int    g_bsum[256];
__device__ int    g_boff[256];
__device__ float  g_stats[L * 2 * C];      // per-layer [sum(C) | sumsq(C)]
// pre-packed fp16 weight fragments in mma.sync per-lane order:
// [l][chunk][kstep(8)][nt16(16)][lane(32)] -> uint2 {b0, b1} (f16x2 each)
#define BPK_PER_CHUNK 4096
__device__ __align__(16) uint2 g_Bpk[L * 2 * BPK_PER_CHUNK];

// ---------------- helpers ----------------
__device__ __forceinline__ uint32_t pack_f16x2(float2 v) {
    __half2 h = __float22half2_rn(v);
    return *(uint32_t*)&h;
}
__device__ __forceinline__ void mma_f16(float* d, const uint32_t* a, uint32_t b0, uint32_t b1) {
    asm volatile(
        "mma.sync.aligned.m16n8k16.row.col.f32.f16.f16.f32 "
        "{%0,%1,%2,%3}, {%4,%5,%6,%7}, {%8,%9}, {%0,%1,%2,%3};"
        : "+f"(d[0]), "+f"(d[1]), "+f"(d[2]), "+f"(d[3])
        : "r"(a[0]), "r"(a[1]), "r"(a[2]), "r"(a[3]), "r"(b0), "r"(b1));
}

// ---------------- prep: zero counters/stats + pre-pack fp16 weight fragments --------
__global__ void k_wprep(const float* __restrict__ Ws, const float* __restrict__ Wn) {
    int i = blockIdx.x * blockDim.x + threadIdx.x;   // 65536 threads
    if (i < N_NODES) g_degcnt[i] = 0;
    if (i < L * 2 * C) g_stats[i] = 0.0f;
    if (i >= L * 2 * BPK_PER_CHUNK) return;
    int lane  = i & 31;
    int nt    = (i >> 5) & 15;
    int kstep = (i >> 9) & 7;
    int chunk = (i >> 12) & 1;
    int l     = i >> 13;
    const float* W = (chunk ? Wn : Ws) + (size_t)l * 16384;
    int k0 = kstep * 16 + (lane & 3) * 2;
    int n  = nt * 8 + (lane >> 2);
    uint32_t b0 = pack_f16x2(make_float2(W[(k0 + 0) * 128 + n], W[(k0 + 1) * 128 + n]));
    uint32_t b1 = pack_f16x2(make_float2(W[(k0 + 8) * 128 + n], W[(k0 + 9) * 128 + n]));
    g_Bpk[i] = make_uint2(b0, b1);
}

__global__ void k_count(const int* __restrict__ dst) {
    int e = blockIdx.x * blockDim.x + threadIdx.x;
    if (e < N_EDGES) atomicAdd(&g_degcnt[dst[e]], 1);
}

// scan phase 1: 256 blocks x 256 threads; block b sums counts [b*256, b*256+256)
__global__ void k_scan1() {
    __shared__ int red[256];
    int b = blockIdx.x, t = threadIdx.x;
    red[t] = g_degcnt[b * 256 + t];
    __syncthreads();
    #pragma unroll
    for (int o = 128; o > 0; o >>= 1) {
        if (t < o) red[t] += red[t + o];
        __syncthreads();
    }
    if (t == 0) g_bsum[b] = red[0];
}
// scan phase 2: 1 block x 256 threads; exclusive scan of 256 block sums
__global__ void k_scan2() {
    __shared__ int sp[256];
    int t = threadIdx.x;
    int v = g_bsum[t];
    sp[t] = v;
    __syncthreads();
    #pragma unroll
    for (int o = 1; o < 256; o <<= 1) {
        int u = (t >= o) ? sp[t - o] : 0;
        __syncthreads();
        sp[t] += u;
        __syncthreads();
    }
    g_boff[t] = sp[t] - v;
    if (t == 0) g_off[N_NODES] = N_EDGES;
}
// scan phase 3: 256 blocks x 256 threads; in-block exclusive scan + finalize
__global__ void k_scan3() {
    __shared__ int sp[256];
    int b = blockIdx.x, t = threadIdx.x;
    int n = b * 256 + t;
    int cnt = g_degcnt[n];
    sp[t] = cnt;
    __syncthreads();
    #pragma unroll
    for (int o = 1; o < 256; o <<= 1) {
        int u = (t >= o) ? sp[t - o] : 0;
        __syncthreads();
        sp[t] += u;
        __syncthreads();
    }
    int off = g_boff[b] + sp[t] - cnt;
    g_off[n] = off;
    g_cursor[n] = off;
    g_deginv[n] = 1.0f / fmaxf((float)cnt, 1.0f);
}

__global__ void k_scatter(const int* __restrict__ src, const int* __restrict__ dst,
                          const float* __restrict__ ew) {
    int e = blockIdx.x * blockDim.x + threadIdx.x;
    if (e >= N_EDGES) return;
    int p = atomicAdd(&g_cursor[dst[e]], 1);
    g_edge[p] = make_float2(__int_as_float(src[e]), log1pf(ew[e]));
}

// ---------------- one-time: BN column stats of x + fp16 copy ----------------
__global__ void k_stats(const float* __restrict__ x) {
    int tid = threadIdx.x;
    int c = tid & (C - 1);
    int rr = tid >> 7;
    float s = 0.0f, s2 = 0.0f;
    for (int r = blockIdx.x * 2 + rr; r < N_NODES; r += gridDim.x * 2) {
        float v = x[(size_t)r * C + c];
        s += v; s2 += v * v;
        g_act16[(size_t)r * C + c] = __float2half_rn(v);
    }
    atomicAdd(&g_stats[c], s);
    atomicAdd(&g_stats[C + c], s2);
}

// ---------------- per-layer: mean aggregation from fp16 buffer, 8-wide -------------
// lane loads uint2 = 4 halves (channels lane*4..+3); 256B per warp per edge.
__global__ void k_aggr() {
    int n = (blockIdx.x * blockDim.x + threadIdx.x) >> 5;
    int lane = threadIdx.x & 31;
    if (n >= N_NODES) return;
    int beg = g_off[n], end = g_off[n + 1];
    const uint2* in2 = (const uint2*)g_act16;   // 32 uint2 per row
    float4 a0 = make_float4(0.f, 0.f, 0.f, 0.f);
    float4 a1 = make_float4(0.f, 0.f, 0.f, 0.f);
    float ws = 0.f;
    int il = end - 1;
    for (int base = beg; base < end; base += 8) {
        float2 e[8];
        uint2 v[8];
        float w[8];
        #pragma unroll
        for (int j = 0; j < 8; j++) e[j] = g_edge[min(base + j, il)];
        #pragma unroll
        for (int j = 0; j < 8; j++)
            v[j] = __ldg(&in2[(size_t)__float_as_int(e[j].x) * 32 + lane]);
        #pragma unroll
        for (int j = 0; j < 8; j++) w[j] = (base + j < end) ? e[j].y : 0.f;
        #pragma unroll
        for (int j = 0; j < 8; j += 2) {
            float2 f0 = __half22float2(*(__half2*)&v[j].x);
            float2 f1 = __half22float2(*(__half2*)&v[j].y);
            a0.x += w[j] * f0.x; a0.y += w[j] * f0.y;
            a0.z += w[j] * f1.x; a0.w += w[j] * f1.y;
            float2 g0 = __half22float2(*(__half2*)&v[j+1].x);
            float2 g1 = __half22float2(*(__half2*)&v[j+1].y);
            a1.x += w[j+1] * g0.x; a1.y += w[j+1] * g0.y;
            a1.z += w[j+1] * g1.x; a1.w += w[j+1] * g1.y;
            ws += w[j] + w[j+1];
        }
    }
    float di = g_deginv[n];
    float4 acc = make_float4((a0.x + a1.x) * di, (a0.y + a1.y) * di,
                             (a0.z + a1.z) * di, (a0.w + a1.w) * di);
    ((float4*)g_neigh)[(size_t)n * 32 + lane] = acc;
    if (lane == 0) g_wbar[n] = ws * di;
}

// ---------------- per-layer: SINGLE-pass fp16 mma.sync dual GEMM, fused BN ----------
// A = fp16(sc*in + sh); B = fp16. 256 MMAs/warp.
// mode 0: write g_h (fp32) + g_act16 (fp16) + next-layer BN stats. mode 1: final dot.
#define GEMM_SMEM (32768 + 2048)

__global__ __launch_bounds__(256, 2)
void k_gemm(int l, const float* __restrict__ Ain,
            const float* __restrict__ gamma, const float* __restrict__ beta,
            const float* __restrict__ bias,
            const float* __restrict__ lin_w, const float* __restrict__ lin_b,
            float* __restrict__ out, int mode) {
    extern __shared__ unsigned char dyn[];
    uint2* sB    = (uint2*)dyn;                 // 32KB: packed fp16 B fragments
    float* sSc   = (float*)(dyn + 32768);       // 128
    float* sSh   = sSc + 128;                   // 128
    float* sStat = sSh + 128;                   // 256

    int tid = threadIdx.x, wid = tid >> 5, lane = tid & 31;
    int row0 = blockIdx.x * 128;

    if (tid < 128) {
        float sum = g_stats[l * 2 * C + tid];
        float sq  = g_stats[l * 2 * C + C + tid];
        float mu  = sum * (1.0f / N_NODES);
        float var = sq * (1.0f / N_NODES) - mu * mu;
        float sc  = gamma[l * C + tid] * rsqrtf(var + BN_EPS);
        sSc[tid] = sc;
        sSh[tid] = beta[l * C + tid] - mu * sc;
    }
    if (tid < 256) sStat[tid] = 0.0f;

    float acc[16][4];
    #pragma unroll
    for (int nt = 0; nt < 16; nt++)
        #pragma unroll
        for (int q = 0; q < 4; q++) acc[nt][q] = 0.0f;

    int ar = row0 + wid * 16 + (lane >> 2);
    int ak = (lane & 3) * 2;
    float wb0 = g_wbar[ar], wb1 = g_wbar[ar + 8];

    #pragma unroll 1
    for (int chunk = 0; chunk < 2; chunk++) {
        if (chunk) __syncthreads();
        {
            const uint4* src = (const uint4*)(g_Bpk + (size_t)(l * 2 + chunk) * BPK_PER_CHUNK);
            uint4* dst = (uint4*)sB;
            #pragma unroll
            for (int it = 0; it < 8; it++) dst[it * 256 + tid] = src[it * 256 + tid];
        }
        __syncthreads();

        const float* Asrc = chunk ? g_neigh : Ain;
        float m0 = chunk ? wb0 : 1.0f;
        float m1 = chunk ? wb1 : 1.0f;
        const float* pbase = Asrc + (size_t)ar * C + ak;

        #pragma unroll 2
        for (int ks = 0; ks < 8; ks++) {
            const float* p = pbase + ks * 16;
            float2 v0 = *(const float2*)(p);
            float2 v1 = *(const float2*)(p + 8 * C);
            float2 v2 = *(const float2*)(p + 8);
            float2 v3 = *(const float2*)(p + 8 * C + 8);

            int kk = ks * 16 + ak;
            float2 scA = *(const float2*)&sSc[kk];
            float2 scB = *(const float2*)&sSc[kk + 8];
            float2 shA = *(const float2*)&sSh[kk];
            float2 shB = *(const float2*)&sSh[kk + 8];

            v0.x = v0.x * scA.x + shA.x * m0; v0.y = v0.y * scA.y + shA.y * m0;
            v1.x = v1.x * scA.x + shA.x * m1; v1.y = v1.y * scA.y + shA.y * m1;
            v2.x = v2.x * scB.x + shB.x * m0; v2.y = v2.y * scB.y + shB.y * m0;
            v3.x = v3.x * scB.x + shB.x * m1; v3.y = v3.y * scB.y + shB.y * m1;

            uint32_t a[4];
            a[0] = pack_f16x2(v0);
            a[1] = pack_f16x2(v1);
            a[2] = pack_f16x2(v2);
            a[3] = pack_f16x2(v3);

            #pragma unroll
            for (int nt = 0; nt < 16; nt++) {
                uint2 b = sB[(ks * 16 + nt) * 32 + lane];
                mma_f16(acc[nt], a, b.x, b.y);
            }
        }
    }

    if (mode == 0) {
        #pragma unroll
        for (int nt = 0; nt < 16; nt++) {
            int col = nt * 8 + (lane & 3) * 2;
            float b0 = bias[col], b1 = bias[col + 1];
            float o00 = fmaxf(acc[nt][0] + b0, 0.f);
            float o01 = fmaxf(acc[nt][1] + b1, 0.f);
            float o10 = fmaxf(acc[nt][2] + b0, 0.f);
            float o11 = fmaxf(acc[nt][3] + b1, 0.f);
            *(float2*)(g_h + (size_t)ar * C + col)       = make_float2(o00, o01);
            *(float2*)(g_h + (size_t)(ar + 8) * C + col) = make_float2(o10, o11);
            *(uint32_t*)(g_act16 + (size_t)ar * C + col) =
                pack_f16x2(make_float2(o00, o01));
            *(uint32_t*)(g_act16 + (size_t)(ar + 8) * C + col) =
                pack_f16x2(make_float2(o10, o11));
            float s0 = o00 + o10, s1 = o01 + o11;
            float q0 = o00 * o00 + o10 * o10, q1 = o01 * o01 + o11 * o11;
            #pragma unroll
            for (int off = 16; off >= 4; off >>= 1) {
                s0 += __shfl_down_sync(0xffffffffu, s0, off);
                s1 += __shfl_down_sync(0xffffffffu, s1, off);
                q0 += __shfl_down_sync(0xffffffffu, q0, off);
                q1 += __shfl_down_sync(0xffffffffu, q1, off);
            }
            if (lane < 4) {
                atomicAdd(&sStat[col],           s0);
                atomicAdd(&sStat[col + 1],       s1);
                atomicAdd(&sStat[128 + col],     q0);
                atomicAdd(&sStat[128 + col + 1], q1);
            }
        }
        __syncthreads();
        if (tid < 128) {
            atomicAdd(&g_stats[(l + 1) * 2 * C + tid],     sStat[tid]);
            atomicAdd(&g_stats[(l + 1) * 2 * C + C + tid], sStat[128 + tid]);
        }
    } else {
        float p0 = 0.f, p1 = 0.f;
        #pragma unroll
        for (int nt = 0; nt < 16; nt++) {
            int col = nt * 8 + (lane & 3) * 2;
            float b0 = bias[col], b1 = bias[col + 1];
            float lw0 = lin_w[col], lw1 = lin_w[col + 1];
            float o00 = fmaxf(acc[nt][0] + b0, 0.f);
            float o01 = fmaxf(acc[nt][1] + b1, 0.f);
            float o10 = fmaxf(acc[nt][2] + b0, 0.f);
            float o11 = fmaxf(acc[nt][3] + b1, 0.f);
            p0 += o00 * lw0 + o01 * lw1;
            p1 += o10 * lw0 + o11 * lw1;
        }
        p0 += __shfl_xor_sync(0xffffffffu, p0, 1);
        p0 += __shfl_xor_sync(0xffffffffu, p0, 2);
        p1 += __shfl_xor_sync(0xffffffffu, p1, 1);
        p1 += __shfl_xor_sync(0xffffffffu, p1, 2);
        if ((lane & 3) == 0) {
            float lb = lin_b[0];
            out[ar] = p0 + lb;
            out[ar + 8] = p1 + lb;
        }
    }
}

// ---------------- launch ----------------
extern "C" void kernel_launch(void* const* d_in, const int* in_sizes, int n_in,
                              void* d_out, int out_size) {
    const float* x      = (const float*)d_in[0];
    const float* ew     = (const float*)d_in[1];
    const float* gamma  = (const float*)d_in[2];
    const float* beta   = (const float*)d_in[3];
    const float* Wself  = (const float*)d_in[4];
    const float* Wneigh = (const float*)d_in[5];
    const float* bias   = (const float*)d_in[6];
    const float* lin_w  = (const float*)d_in[7];
    const float* lin_b  = (const float*)d_in[8];
    const int*   src    = (const int*)d_in[9];
    const int*   dst    = (const int*)d_in[10];
    float*       out    = (float*)d_out;

    (void)in_sizes; (void)n_in; (void)out_size;

    cudaFuncSetAttribute(k_gemm, cudaFuncAttributeMaxDynamicSharedMemorySize, GEMM_SMEM);

    float* hdev = nullptr;
    cudaGetSymbolAddress((void**)&hdev, g_h);

    k_wprep  <<<N_NODES / 256, 256>>>(Wself, Wneigh);   // zero + weight pack
    k_count  <<<N_EDGES / 256, 256>>>(dst);
    k_scan1  <<<256, 256>>>();
    k_scan2  <<<1, 256>>>();
    k_scan3  <<<256, 256>>>();
    k_scatter<<<N_EDGES / 256, 256>>>(src, dst, ew);
    k_stats  <<<256, 256>>>(x);

    for (int l = 0; l < L; l++) {
        const float* in = (l == 0) ? x : hdev;
        k_aggr<<<N_NODES * 32 / 256, 256>>>();
        k_gemm<<<N_NODES / 128, 256, GEMM_SMEM>>>(l, in, gamma, beta,
                                                  bias + (size_t)l * C,
                                                  lin_w, lin_b, out,
                                                  (l == L - 1) ? 1 : 0);
    }
}

// round 17
// speedup vs baseline: 1.2383x; 1.2383x over previous
#include <cuda_runtime.h>
#include <cuda_fp16.h>
#include <math.h>
#include <stdint.h>

#define N_NODES 65536
#define N_EDGES 524288
#define C 128
#define L 3
#define BN_EPS 1e-5f

// ---------------- scratch (device globals; zero-initialized at module load) --------
__device__ __half g_act16[N_NODES * C];    // activations (fp16, ONLY copy)
__device__ __half g_neigh16[N_NODES * C];  // aggregated neighbor features (fp16)
__device__ float  g_wbar[N_NODES];         // (sum of edge weights)/deg per node
__device__ float2 g_edge[N_EDGES];         // CSR-by-dst packed: (src bits, log1p(w))
__device__ int    g_degcnt[N_NODES];       // zero at module load; scan3 re-zeros
__device__ int    g_off[N_NODES + 1];
__device__ int    g_cursor[N_NODES];
__device__ float  g_deginv[N_NODES];
__device__ int    g_bsum[256];
__device__ int    g_boff[256];
__device__ float  g_stats[L * 2 * C];      // per-layer [sum(C) | sumsq(C)]
// pre-packed fp16 weight fragments in mma.sync per-lane order:
// [l][chunk][kstep(8)][nt16(16)][lane(32)] -> uint2 {b0, b1}
#define BPK_PER_CHUNK 4096
__device__ __align__(16) uint2 g_Bpk[L * 2 * BPK_PER_CHUNK];

// ---------------- helpers ----------------
__device__ __forceinline__ uint32_t pack_f16x2(float2 v) {
    __half2 h = __float22half2_rn(v);
    return *(uint32_t*)&h;
}
__device__ __forceinline__ float2 unpack_f16x2(uint32_t r) {
    return __half22float2(*(__half2*)&r);
}
__device__ __forceinline__ void mma_f16(float* d, const uint32_t* a, uint32_t b0, uint32_t b1) {
    asm volatile(
        "mma.sync.aligned.m16n8k16.row.col.f32.f16.f16.f32 "
        "{%0,%1,%2,%3}, {%4,%5,%6,%7}, {%8,%9}, {%0,%1,%2,%3};"
        : "+f"(d[0]), "+f"(d[1]), "+f"(d[2]), "+f"(d[3])
        : "r"(a[0]), "r"(a[1]), "r"(a[2]), "r"(a[3]), "r"(b0), "r"(b1));
}

// ---------------- kernel 1: edge counting + (extra blocks) weight pack + stats zero -
// blocks [0, 2048): count edges. blocks [2048, 2144): pack weights; zero g_stats.
__global__ void k_count(const int* __restrict__ dst,
                        const float* __restrict__ Ws, const float* __restrict__ Wn) {
    int b = blockIdx.x, t = threadIdx.x;
    if (b < 2048) {
        atomicAdd(&g_degcnt[dst[b * 256 + t]], 1);
        return;
    }
    int i = (b - 2048) * 256 + t;              // 0 .. 24575
    if (i < L * 2 * C) g_stats[i] = 0.0f;
    int lane  = i & 31;
    int nt    = (i >> 5) & 15;
    int kstep = (i >> 9) & 7;
    int chunk = (i >> 12) & 1;
    int l     = i >> 13;
    const float* W = (chunk ? Wn : Ws) + (size_t)l * 16384;
    int k0 = kstep * 16 + (lane & 3) * 2;
    int n  = nt * 8 + (lane >> 2);
    uint32_t b0 = pack_f16x2(make_float2(W[(k0 + 0) * 128 + n], W[(k0 + 1) * 128 + n]));
    uint32_t b1 = pack_f16x2(make_float2(W[(k0 + 8) * 128 + n], W[(k0 + 9) * 128 + n]));
    g_Bpk[i] = make_uint2(b0, b1);
}

// scan phase 1: 256 blocks; block b sums counts [b*256, b*256+256)
__global__ void k_scan1() {
    __shared__ int red[256];
    int b = blockIdx.x, t = threadIdx.x;
    red[t] = g_degcnt[b * 256 + t];
    __syncthreads();
    #pragma unroll
    for (int o = 128; o > 0; o >>= 1) {
        if (t < o) red[t] += red[t + o];
        __syncthreads();
    }
    if (t == 0) g_bsum[b] = red[0];
}
// scan phase 2: 1 block; exclusive scan of 256 block sums
__global__ void k_scan2() {
    __shared__ int sp[256];
    int t = threadIdx.x;
    int v = g_bsum[t];
    sp[t] = v;
    __syncthreads();
    #pragma unroll
    for (int o = 1; o < 256; o <<= 1) {
        int u = (t >= o) ? sp[t - o] : 0;
        __syncthreads();
        sp[t] += u;
        __syncthreads();
    }
    g_boff[t] = sp[t] - v;
    if (t == 0) g_off[N_NODES] = N_EDGES;
}
// scan phase 3: 256 blocks; in-block exclusive scan + finalize + reset degcnt
__global__ void k_scan3() {
    __shared__ int sp[256];
    int b = blockIdx.x, t = threadIdx.x;
    int n = b * 256 + t;
    int cnt = g_degcnt[n];
    g_degcnt[n] = 0;                        // reset for next replay (zero at load too)
    sp[t] = cnt;
    __syncthreads();
    #pragma unroll
    for (int o = 1; o < 256; o <<= 1) {
        int u = (t >= o) ? sp[t - o] : 0;
        __syncthreads();
        sp[t] += u;
        __syncthreads();
    }
    int off = g_boff[b] + sp[t] - cnt;
    g_off[n] = off;
    g_cursor[n] = off;
    g_deginv[n] = 1.0f / fmaxf((float)cnt, 1.0f);
}

// ---------------- kernel 5: scatter + (extra blocks) BN stats of x + fp16 copy -----
// blocks [0, 2048): scatter. blocks [2048, 2304): column stats + act16 init.
__global__ void k_scatter(const int* __restrict__ src, const int* __restrict__ dst,
                          const float* __restrict__ ew, const float* __restrict__ x) {
    int b = blockIdx.x, t = threadIdx.x;
    if (b < 2048) {
        int e = b * 256 + t;
        int p = atomicAdd(&g_cursor[dst[e]], 1);
        g_edge[p] = make_float2(__int_as_float(src[e]), log1pf(ew[e]));
        return;
    }
    int sb = b - 2048;                       // 0..255
    int c = t & (C - 1);
    int rr = t >> 7;
    float s = 0.0f, s2 = 0.0f;
    for (int r = sb * 2 + rr; r < N_NODES; r += 512) {
        float v = x[(size_t)r * C + c];
        s += v; s2 += v * v;
        g_act16[(size_t)r * C + c] = __float2half_rn(v);
    }
    atomicAdd(&g_stats[c], s);
    atomicAdd(&g_stats[C + c], s2);
}

// ---------------- per-layer: mean aggregation (fp16 in, fp16 out), 8-wide ----------
__global__ void k_aggr() {
    int n = (blockIdx.x * blockDim.x + threadIdx.x) >> 5;
    int lane = threadIdx.x & 31;
    if (n >= N_NODES) return;
    int beg = g_off[n], end = g_off[n + 1];
    const uint2* in2 = (const uint2*)g_act16;   // 32 uint2 per row
    float4 a0 = make_float4(0.f, 0.f, 0.f, 0.f);
    float4 a1 = make_float4(0.f, 0.f, 0.f, 0.f);
    float ws = 0.f;
    int il = end - 1;
    for (int base = beg; base < end; base += 8) {
        float2 e[8];
        uint2 v[8];
        float w[8];
        #pragma unroll
        for (int j = 0; j < 8; j++) e[j] = g_edge[min(base + j, il)];
        #pragma unroll
        for (int j = 0; j < 8; j++)
            v[j] = __ldg(&in2[(size_t)__float_as_int(e[j].x) * 32 + lane]);
        #pragma unroll
        for (int j = 0; j < 8; j++) w[j] = (base + j < end) ? e[j].y : 0.f;
        #pragma unroll
        for (int j = 0; j < 8; j += 2) {
            float2 f0 = unpack_f16x2(v[j].x);
            float2 f1 = unpack_f16x2(v[j].y);
            a0.x += w[j] * f0.x; a0.y += w[j] * f0.y;
            a0.z += w[j] * f1.x; a0.w += w[j] * f1.y;
            float2 g0 = unpack_f16x2(v[j+1].x);
            float2 g1 = unpack_f16x2(v[j+1].y);
            a1.x += w[j+1] * g0.x; a1.y += w[j+1] * g0.y;
            a1.z += w[j+1] * g1.x; a1.w += w[j+1] * g1.y;
            ws += w[j] + w[j+1];
        }
    }
    float di = g_deginv[n];
    uint2 o;
    o.x = pack_f16x2(make_float2((a0.x + a1.x) * di, (a0.y + a1.y) * di));
    o.y = pack_f16x2(make_float2((a0.z + a1.z) * di, (a0.w + a1.w) * di));
    ((uint2*)g_neigh16)[(size_t)n * 32 + lane] = o;
    if (lane == 0) g_wbar[n] = ws * di;
}

// ---------------- per-layer: fp16 mma.sync dual GEMM, fp16-only activations ---------
// A read from g_act16 / g_neigh16 (fp16), affine in fp32, repacked fp16.
// mode 0: write g_act16 only + next-layer BN stats. mode 1: fused final dot -> out.
#define GEMM_SMEM (32768 + 2048)

__global__ __launch_bounds__(256, 2)
void k_gemm(int l,
            const float* __restrict__ gamma, const float* __restrict__ beta,
            const float* __restrict__ bias,
            const float* __restrict__ lin_w, const float* __restrict__ lin_b,
            float* __restrict__ out, int mode) {
    extern __shared__ unsigned char dyn[];
    uint2* sB    = (uint2*)dyn;                 // 32KB: packed fp16 B fragments
    float* sSc   = (float*)(dyn + 32768);       // 128
    float* sSh   = sSc + 128;                   // 128
    float* sStat = sSh + 128;                   // 256

    int tid = threadIdx.x, wid = tid >> 5, lane = tid & 31;
    int row0 = blockIdx.x * 128;

    if (tid < 128) {
        float sum = g_stats[l * 2 * C + tid];
        float sq  = g_stats[l * 2 * C + C + tid];
        float mu  = sum * (1.0f / N_NODES);
        float var = sq * (1.0f / N_NODES) - mu * mu;
        float sc  = gamma[l * C + tid] * rsqrtf(var + BN_EPS);
        sSc[tid] = sc;
        sSh[tid] = beta[l * C + tid] - mu * sc;
    }
    if (tid < 256) sStat[tid] = 0.0f;

    float acc[16][4];
    #pragma unroll
    for (int nt = 0; nt < 16; nt++)
        #pragma unroll
        for (int q = 0; q < 4; q++) acc[nt][q] = 0.0f;

    int ar = row0 + wid * 16 + (lane >> 2);   // A fragment base row (this + ar+8)
    int ak = (lane & 3) * 2;
    float wb0 = g_wbar[ar], wb1 = g_wbar[ar + 8];

    #pragma unroll 1
    for (int chunk = 0; chunk < 2; chunk++) {
        if (chunk) __syncthreads();
        {
            const uint4* srcp = (const uint4*)(g_Bpk + (size_t)(l * 2 + chunk) * BPK_PER_CHUNK);
            uint4* dstp = (uint4*)sB;
            #pragma unroll
            for (int it = 0; it < 8; it++) dstp[it * 256 + tid] = srcp[it * 256 + tid];
        }
        __syncthreads();

        const __half* Ah = chunk ? g_neigh16 : g_act16;
        float m0 = chunk ? wb0 : 1.0f;
        float m1 = chunk ? wb1 : 1.0f;
        const __half* pbase = Ah + (size_t)ar * C + ak;

        #pragma unroll 2
        for (int ks = 0; ks < 8; ks++) {
            const __half* p = pbase + ks * 16;
            float2 v0 = unpack_f16x2(*(const uint32_t*)(p));
            float2 v1 = unpack_f16x2(*(const uint32_t*)(p + 8 * C));
            float2 v2 = unpack_f16x2(*(const uint32_t*)(p + 8));
            float2 v3 = unpack_f16x2(*(const uint32_t*)(p + 8 * C + 8));

            int kk = ks * 16 + ak;
            float2 scA = *(const float2*)&sSc[kk];
            float2 scB = *(const float2*)&sSc[kk + 8];
            float2 shA = *(const float2*)&sSh[kk];
            float2 shB = *(const float2*)&sSh[kk + 8];

            v0.x = v0.x * scA.x + shA.x * m0; v0.y = v0.y * scA.y + shA.y * m0;
            v1.x = v1.x * scA.x + shA.x * m1; v1.y = v1.y * scA.y + shA.y * m1;
            v2.x = v2.x * scB.x + shB.x * m0; v2.y = v2.y * scB.y + shB.y * m0;
            v3.x = v3.x * scB.x + shB.x * m1; v3.y = v3.y * scB.y + shB.y * m1;

            uint32_t a[4];
            a[0] = pack_f16x2(v0);
            a[1] = pack_f16x2(v1);
            a[2] = pack_f16x2(v2);
            a[3] = pack_f16x2(v3);

            #pragma unroll
            for (int nt = 0; nt < 16; nt++) {
                uint2 b = sB[(ks * 16 + nt) * 32 + lane];
                mma_f16(acc[nt], a, b.x, b.y);
            }
        }
    }

    if (mode == 0) {
        // epilogue: bias + ReLU -> g_act16 (fp16 only), next-layer BN stats (fp32)
        #pragma unroll
        for (int nt = 0; nt < 16; nt++) {
            int col = nt * 8 + (lane & 3) * 2;
            float b0 = bias[col], b1 = bias[col + 1];
            float o00 = fmaxf(acc[nt][0] + b0, 0.f);
            float o01 = fmaxf(acc[nt][1] + b1, 0.f);
            float o10 = fmaxf(acc[nt][2] + b0, 0.f);
            float o11 = fmaxf(acc[nt][3] + b1, 0.f);
            *(uint32_t*)(g_act16 + (size_t)ar * C + col) =
                pack_f16x2(make_float2(o00, o01));
            *(uint32_t*)(g_act16 + (size_t)(ar + 8) * C + col) =
                pack_f16x2(make_float2(o10, o11));
            float s0 = o00 + o10, s1 = o01 + o11;
            float q0 = o00 * o00 + o10 * o10, q1 = o01 * o01 + o11 * o11;
            #pragma unroll
            for (int off = 16; off >= 4; off >>= 1) {
                s0 += __shfl_down_sync(0xffffffffu, s0, off);
                s1 += __shfl_down_sync(0xffffffffu, s1, off);
                q0 += __shfl_down_sync(0xffffffffu, q0, off);
                q1 += __shfl_down_sync(0xffffffffu, q1, off);
            }
            if (lane < 4) {
                atomicAdd(&sStat[col],           s0);
                atomicAdd(&sStat[col + 1],       s1);
                atomicAdd(&sStat[128 + col],     q0);
                atomicAdd(&sStat[128 + col + 1], q1);
            }
        }
        __syncthreads();
        if (tid < 128) {
            atomicAdd(&g_stats[(l + 1) * 2 * C + tid],     sStat[tid]);
            atomicAdd(&g_stats[(l + 1) * 2 * C + C + tid], sStat[128 + tid]);
        }
    } else {
        // last layer: fused final dot over this warp's 16 rows
        float p0 = 0.f, p1 = 0.f;
        #pragma unroll
        for (int nt = 0; nt < 16; nt++) {
            int col = nt * 8 + (lane & 3) * 2;
            float b0 = bias[col], b1 = bias[col + 1];
            float lw0 = lin_w[col], lw1 = lin_w[col + 1];
            float o00 = fmaxf(acc[nt][0] + b0, 0.f);
            float o01 = fmaxf(acc[nt][1] + b1, 0.f);
            float o10 = fmaxf(acc[nt][2] + b0, 0.f);
            float o11 = fmaxf(acc[nt][3] + b1, 0.f);
            p0 += o00 * lw0 + o01 * lw1;
            p1 += o10 * lw0 + o11 * lw1;
        }
        p0 += __shfl_xor_sync(0xffffffffu, p0, 1);
        p0 += __shfl_xor_sync(0xffffffffu, p0, 2);
        p1 += __shfl_xor_sync(0xffffffffu, p1, 1);
        p1 += __shfl_xor_sync(0xffffffffu, p1, 2);
        if ((lane & 3) == 0) {
            float lb = lin_b[0];
            out[ar] = p0 + lb;
            out[ar + 8] = p1 + lb;
        }
    }
}

// ---------------- launch (11 kernel nodes) ----------------
extern "C" void kernel_launch(void* const* d_in, const int* in_sizes, int n_in,
                              void* d_out, int out_size) {
    const float* x      = (const float*)d_in[0];
    const float* ew     = (const float*)d_in[1];
    const float* gamma  = (const float*)d_in[2];
    const float* beta   = (const float*)d_in[3];
    const float* Wself  = (const float*)d_in[4];
    const float* Wneigh = (const float*)d_in[5];
    const float* bias   = (const float*)d_in[6];
    const float* lin_w  = (const float*)d_in[7];
    const float* lin_b  = (const float*)d_in[8];
    const int*   src    = (const int*)d_in[9];
    const int*   dst    = (const int*)d_in[10];
    float*       out    = (float*)d_out;

    (void)in_sizes; (void)n_in; (void)out_size;

    cudaFuncSetAttribute(k_gemm, cudaFuncAttributeMaxDynamicSharedMemorySize, GEMM_SMEM);

    k_count  <<<2048 + 96, 256>>>(dst, Wself, Wneigh);   // count + wpack + stats zero
    k_scan1  <<<256, 256>>>();
    k_scan2  <<<1, 256>>>();
    k_scan3  <<<256, 256>>>();                           // offsets + degcnt reset
    k_scatter<<<2048 + 256, 256>>>(src, dst, ew, x);     // scatter + x stats/act16

    for (int l = 0; l < L; l++) {
        k_aggr<<<N_NODES * 32 / 256, 256>>>();
        k_gemm<<<N_NODES / 128, 256, GEMM_SMEM>>>(l, gamma, beta,
                                                  bias + (size_t)l * C,
                                                  lin_w, lin_b, out,
                                                  (l == L - 1) ? 1 : 0);
    }
}